// round 3
// baseline (speedup 1.0000x reference)
#include <cuda_runtime.h>

// Problem constants
#define BB 128
#define SS 512
#define UU 1024
#define TT 48

// Scratch (device globals — no runtime allocation)
__device__ float g_scores[BB * SS * TT];   // 12.6 MB, fp32 scores
__device__ float g_num[BB];                // numerator per batch

// ---------------------------------------------------------------------------
// Packed fp32x2 FMA (Blackwell FFMA2). Lanewise: d.lo += a.lo*b.lo, d.hi += a.hi*b.hi
// ---------------------------------------------------------------------------
__device__ __forceinline__ void fma2(unsigned long long& d,
                                     unsigned long long a,
                                     unsigned long long b) {
    asm("fma.rn.f32x2 %0, %1, %2, %0;" : "+l"(d) : "l"(a), "l"(b));
}

// ---------------------------------------------------------------------------
// GEMM: g_scores[m][t] = sum_k H[m][k] * W[k][t] + bias[t]
// M = B*S = 65536, K = 1024, N = 48.
// Block tile: 128 rows x 48 cols, Kc = 32 per chunk, k-pairs packed in f32x2.
// Hs layout: [m][k2] with row stride 17 float2 (pad avoids bank conflicts).
// Ws layout: [k2][n] float2 = (W[2k2][n], W[2k2+1][n]).
// Thread (tm=tid>>3, tn=tid&7) computes 4 rows x 6 cols.
// ---------------------------------------------------------------------------
__global__ __launch_bounds__(256, 2)
void gemm_kernel(const float* __restrict__ H,
                 const float* __restrict__ W,
                 const float* __restrict__ bias) {
    __shared__ __align__(16) float2 Hs[128 * 17];
    __shared__ __align__(16) float2 Ws[16 * 48];

    const int tid = threadIdx.x;
    const int rowBase = blockIdx.x * 128;

    // Global->smem load mapping (coalesced 128B row chunks for H)
    const int lrow = tid >> 3;           // 0..31 (4 rows per thread: +32*i)
    const int lkq  = tid & 7;            // k offset = lkq*4 within 32-chunk
    const int wk2  = tid >> 4;           // 0..15
    const int wn   = (tid & 15) * 3;     // 0..45

    // Compute mapping
    const int tn = tid & 7;              // col block
    const int tm = tid >> 3;             // row block
    const int n0 = tn * 6;
    const int m0 = tm * 4;

    float bias_l[6];
#pragma unroll
    for (int j = 0; j < 6; j++) bias_l[j] = bias[n0 + j];

    unsigned long long acc[4][6];
#pragma unroll
    for (int r = 0; r < 4; r++)
#pragma unroll
        for (int j = 0; j < 6; j++) acc[r][j] = 0ull;

    float4 hreg[4];
    float  wreg[6];

    // load chunk 0 into regs
#pragma unroll
    for (int i = 0; i < 4; i++)
        hreg[i] = *reinterpret_cast<const float4*>(
            H + (size_t)(rowBase + lrow + 32 * i) * UU + lkq * 4);
#pragma unroll
    for (int j = 0; j < 3; j++) {
        wreg[2 * j]     = W[(wk2 * 2) * TT + wn + j];
        wreg[2 * j + 1] = W[(wk2 * 2 + 1) * TT + wn + j];
    }
    // stage chunk 0 to smem
#pragma unroll
    for (int i = 0; i < 4; i++) {
        int m = lrow + 32 * i;
        Hs[m * 17 + lkq * 2]     = make_float2(hreg[i].x, hreg[i].y);
        Hs[m * 17 + lkq * 2 + 1] = make_float2(hreg[i].z, hreg[i].w);
    }
#pragma unroll
    for (int j = 0; j < 3; j++)
        Ws[wk2 * TT + wn + j] = make_float2(wreg[2 * j], wreg[2 * j + 1]);
    __syncthreads();

    for (int c = 0; c < 32; c++) {
        if (c < 31) {
            const int kc = (c + 1) * 32;
#pragma unroll
            for (int i = 0; i < 4; i++)
                hreg[i] = *reinterpret_cast<const float4*>(
                    H + (size_t)(rowBase + lrow + 32 * i) * UU + kc + lkq * 4);
#pragma unroll
            for (int j = 0; j < 3; j++) {
                wreg[2 * j]     = W[(kc + wk2 * 2) * TT + wn + j];
                wreg[2 * j + 1] = W[(kc + wk2 * 2 + 1) * TT + wn + j];
            }
        }
        const unsigned long long* HsU =
            reinterpret_cast<const unsigned long long*>(Hs);
#pragma unroll
        for (int k2 = 0; k2 < 16; k2++) {
            unsigned long long a[4];
#pragma unroll
            for (int r = 0; r < 4; r++) a[r] = HsU[(m0 + r) * 17 + k2];
            const ulonglong2* bp =
                reinterpret_cast<const ulonglong2*>(Ws + k2 * TT + n0);
            ulonglong2 b01 = bp[0], b23 = bp[1], b45 = bp[2];
#pragma unroll
            for (int r = 0; r < 4; r++) {
                fma2(acc[r][0], a[r], b01.x);
                fma2(acc[r][1], a[r], b01.y);
                fma2(acc[r][2], a[r], b23.x);
                fma2(acc[r][3], a[r], b23.y);
                fma2(acc[r][4], a[r], b45.x);
                fma2(acc[r][5], a[r], b45.y);
            }
        }
        __syncthreads();
        if (c < 31) {
#pragma unroll
            for (int i = 0; i < 4; i++) {
                int m = lrow + 32 * i;
                Hs[m * 17 + lkq * 2]     = make_float2(hreg[i].x, hreg[i].y);
                Hs[m * 17 + lkq * 2 + 1] = make_float2(hreg[i].z, hreg[i].w);
            }
#pragma unroll
            for (int j = 0; j < 3; j++)
                Ws[wk2 * TT + wn + j] = make_float2(wreg[2 * j], wreg[2 * j + 1]);
            __syncthreads();
        }
    }

    // Epilogue: reduce even/odd halves, add bias, coalesced float2 stores
#pragma unroll
    for (int r = 0; r < 4; r++) {
        float o[6];
#pragma unroll
        for (int j = 0; j < 6; j++) {
            float2 f = *reinterpret_cast<float2*>(&acc[r][j]);
            o[j] = f.x + f.y + bias_l[j];
        }
        float* dst = g_scores + (size_t)(rowBase + m0 + r) * TT + n0;
        *reinterpret_cast<float2*>(dst + 0) = make_float2(o[0], o[1]);
        *reinterpret_cast<float2*>(dst + 2) = make_float2(o[2], o[3]);
        *reinterpret_cast<float2*>(dst + 4) = make_float2(o[4], o[5]);
    }
}

// ---------------------------------------------------------------------------
// Numerator: per batch
//   num = start[tag0] + sum_{s<len} scores[s][tag[s]]
//       + sum_{1<=s<len} trans[tag[s-1]][tag[s]] + end[tag[len-1]]
// ---------------------------------------------------------------------------
__global__ void num_kernel(const float* __restrict__ trans,
                           const float* __restrict__ startT,
                           const float* __restrict__ endT,
                           const int* __restrict__ tag,
                           const int* __restrict__ s_len) {
    const int b = blockIdx.x;
    const int tid = threadIdx.x;
    const int len = s_len[b];
    const int* tg = tag + b * SS;
    const float* sc = g_scores + (size_t)b * SS * TT;

    float local = 0.f;
    for (int s = tid; s < len; s += 256) {
        int tc = tg[s];
        local += sc[s * TT + tc];
        if (s >= 1) local += trans[tg[s - 1] * TT + tc];
    }
    if (tid == 0) local += startT[tg[0]] + endT[tg[len - 1]];

#pragma unroll
    for (int o = 16; o > 0; o >>= 1)
        local += __shfl_down_sync(0xffffffffu, local, o);
    __shared__ float red[8];
    if ((tid & 31) == 0) red[tid >> 5] = local;
    __syncthreads();
    if (tid < 8) {
        float v = red[tid];
#pragma unroll
        for (int o = 4; o > 0; o >>= 1)
            v += __shfl_down_sync(0x000000ffu, v, o);
        if (tid == 0) g_num[b] = v;
    }
}

// ---------------------------------------------------------------------------
// Forward scan in linear domain with per-step renormalization folded into exp:
//   v'[t'] = exp(emit[t'] - log v[0]) * sum_t v[t] * E[t][t'],  C += log v[0]
// E[t][t'] = exp(trans[t][t']) lives in 48 registers per thread (one column).
// log v[0] cancels exactly in (log v' + C), so only fp32 rounding accumulates.
// Loop runs to s_len[b] (identical to the reference's masked updates).
// out[b] = g_num[b] - (C + log(sum_t v[t]*exp(end[t])))
// One block of 48 threads per batch.
// ---------------------------------------------------------------------------
__global__ void scan_kernel(const float* __restrict__ trans,
                            const float* __restrict__ startT,
                            const float* __restrict__ endT,
                            const int* __restrict__ s_len,
                            float* __restrict__ out) {
    const int b = blockIdx.x;
    const int t = threadIdx.x;   // destination state t'
    __shared__ __align__(16) float vbuf[2][TT];
    __shared__ float red[TT];

    float E[TT];
#pragma unroll
    for (int k = 0; k < TT; k++) E[k] = __expf(trans[k * TT + t]);

    const int len = s_len[b];
    const float* sc = g_scores + (size_t)b * SS * TT;

    float lp0 = startT[t] + sc[t];
    vbuf[0][t] = __expf(lp0);
    double C = 0.0;

    // prefetch emissions two steps ahead (always-valid addresses)
    float e1 = sc[1 * TT + t];
    float e2 = sc[2 * TT + t];
    __syncthreads();

    int cur = 0;
    for (int s = 1; s < len; ++s) {
        float emit = e1;
        e1 = e2;
        int sp = s + 2; if (sp > SS - 1) sp = SS - 1;
        e2 = sc[sp * TT + t];

        const float4* vp = reinterpret_cast<const float4*>(vbuf[cur]);
        float4 q = vp[0];
        float v0 = q.x;
        float a0 = q.x * E[0];
        float a1 = q.y * E[1];
        float a2 = q.z * E[2];
        float a3 = q.w * E[3];
#pragma unroll
        for (int j = 1; j < 12; j++) {
            q = vp[j];
            a0 = fmaf(q.x, E[4 * j + 0], a0);
            a1 = fmaf(q.y, E[4 * j + 1], a1);
            a2 = fmaf(q.z, E[4 * j + 2], a2);
            a3 = fmaf(q.w, E[4 * j + 3], a3);
        }
        float sum = (a0 + a2) + (a1 + a3);

        float lv = __logf(v0);
        C += (double)lv;
        float nv = sum * __expf(emit - lv);

        vbuf[cur ^ 1][t] = nv;
        __syncthreads();
        cur ^= 1;
    }

    // log_Z and final output
    red[t] = vbuf[cur][t] * __expf(endT[t]);
    __syncthreads();
    if (t == 0) {
        float ssum = 0.f;
#pragma unroll
        for (int k = 0; k < TT; k++) ssum += red[k];
        float logZ = (float)C + __logf(ssum);
        out[b] = g_num[b] - logZ;
    }
}

// ---------------------------------------------------------------------------
// Launch. Inputs (metadata order): H, W, b, start_transitions, end_transitions,
// transitions, tag(int32), s_len(int32), w_mask (unused: mask == s < s_len).
// ---------------------------------------------------------------------------
extern "C" void kernel_launch(void* const* d_in, const int* in_sizes, int n_in,
                              void* d_out, int out_size) {
    const float* H      = (const float*)d_in[0];
    const float* W      = (const float*)d_in[1];
    const float* bias   = (const float*)d_in[2];
    const float* startT = (const float*)d_in[3];
    const float* endT   = (const float*)d_in[4];
    const float* trans  = (const float*)d_in[5];
    const int*   tag    = (const int*)d_in[6];
    const int*   s_len  = (const int*)d_in[7];
    (void)in_sizes; (void)n_in; (void)out_size;
    float* out = (float*)d_out;

    gemm_kernel<<<(BB * SS) / 128, 256>>>(H, W, bias);
    num_kernel<<<BB, 256>>>(trans, startT, endT, tag, s_len);
    scan_kernel<<<BB, TT>>>(trans, startT, endT, s_len, out);
}

// round 5
// speedup vs baseline: 1.6200x; 1.6200x over previous
#include <cuda_runtime.h>
#include <cuda_bf16.h>
#include <cstdint>

// Problem constants
#define BB 128
#define SS 512
#define UU 1024
#define TT 48

// Scratch (device globals — no runtime allocation)
__device__ float g_scores[BB * SS * TT];            // fp32 scores, 12.6 MB
// W pre-baked into mma.sync B-fragment layout:
// [s2 (32)][j (6)][lane (32)] uint4 = {b0,b1 of k-step 2*s2, b0,b1 of 2*s2+1}
__device__ __align__(16) uint4 g_Wfrag[32 * 6 * 32];

__device__ __forceinline__ uint32_t packbf(float a, float b) {
    __nv_bfloat162 h = __float22bfloat162_rn(make_float2(a, b));
    return *reinterpret_cast<uint32_t*>(&h);
}

__device__ __forceinline__ void mma16816(float d[4],
                                         uint32_t a0, uint32_t a1,
                                         uint32_t a2, uint32_t a3,
                                         uint32_t b0, uint32_t b1) {
    asm volatile(
        "mma.sync.aligned.m16n8k16.row.col.f32.bf16.bf16.f32 "
        "{%0,%1,%2,%3}, {%4,%5,%6,%7}, {%8,%9}, {%0,%1,%2,%3};"
        : "+f"(d[0]), "+f"(d[1]), "+f"(d[2]), "+f"(d[3])
        : "r"(a0), "r"(a1), "r"(a2), "r"(a3), "r"(b0), "r"(b1));
}

// ---------------------------------------------------------------------------
// One-shot: bake W [U][T] into B fragments (bf16) for mma.sync.
// B frag (n8k16 "col"): lane t: b0 = W[k0+2c .. +1][n], b1 = W[k0+8+2c ..][n],
// with c = t&3, n = 8j + (t>>2).
// ---------------------------------------------------------------------------
__global__ void wfrag_kernel(const float* __restrict__ W) {
    int idx = blockIdx.x * 256 + threadIdx.x;     // 0 .. 64*6*32-1
    if (idx >= 64 * 6 * 32) return;
    int lane = idx & 31;
    int j    = (idx >> 5) % 6;
    int s    = idx / (6 * 32);                    // k-step 0..63
    int c    = lane & 3;
    int n    = 8 * j + (lane >> 2);
    int k0   = 16 * s + 2 * c;
    uint32_t b0 = packbf(W[(size_t)k0 * TT + n],       W[(size_t)(k0 + 1) * TT + n]);
    uint32_t b1 = packbf(W[(size_t)(k0 + 8) * TT + n], W[(size_t)(k0 + 9) * TT + n]);
    int s2 = s >> 1, h = s & 1;
    uint32_t* out = reinterpret_cast<uint32_t*>(&g_Wfrag[(s2 * 6 + j) * 32 + lane]);
    out[h * 2 + 0] = b0;
    out[h * 2 + 1] = b1;
}

// ---------------------------------------------------------------------------
// GEMM via mma.sync bf16: g_scores[m][t] = sum_k bf16(H[m][k])*bf16(W[k][t]) + b[t]
// 256 threads = 8 warps; warp w owns rows [blk*128 + 16w, +16).
// No shared memory, no barriers in the loop. A loaded straight from global.
// ---------------------------------------------------------------------------
__global__ __launch_bounds__(256)
void gemm_mma(const float* __restrict__ H, const float* __restrict__ bias) {
    const int tid  = threadIdx.x;
    const int w    = tid >> 5;
    const int lane = tid & 31;
    const int c    = lane & 3;       // 0..3
    const int g    = lane >> 2;      // 0..7

    const size_t m0 = (size_t)blockIdx.x * 128 + w * 16;
    const float* h0 = H + (m0 + g) * UU;          // row g
    const float* h1 = h0 + 8 * UU;                // row g+8

    float2 bias2[6];
#pragma unroll
    for (int j = 0; j < 6; j++)
        bias2[j] = *reinterpret_cast<const float2*>(bias + 8 * j + 2 * c);

    float d[6][4];
#pragma unroll
    for (int j = 0; j < 6; j++)
#pragma unroll
        for (int i = 0; i < 4; i++) d[j][i] = 0.f;

#pragma unroll 2
    for (int s2 = 0; s2 < 32; ++s2) {
        // B fragments for 2 k16-steps (coalesced, L1/L2-resident)
        uint4 bf[6];
        const uint4* bp = g_Wfrag + s2 * 6 * 32 + lane;
#pragma unroll
        for (int j = 0; j < 6; j++) bf[j] = bp[j * 32];

        const int k0 = s2 * 32;
        float2 A[2][4];
#pragma unroll
        for (int h = 0; h < 2; h++) {
            const int k = k0 + 16 * h;
            A[h][0] = *reinterpret_cast<const float2*>(h0 + k + 2 * c);
            A[h][1] = *reinterpret_cast<const float2*>(h1 + k + 2 * c);
            A[h][2] = *reinterpret_cast<const float2*>(h0 + k + 8 + 2 * c);
            A[h][3] = *reinterpret_cast<const float2*>(h1 + k + 8 + 2 * c);
        }
#pragma unroll
        for (int h = 0; h < 2; h++) {
            uint32_t a0 = packbf(A[h][0].x, A[h][0].y);
            uint32_t a1 = packbf(A[h][1].x, A[h][1].y);
            uint32_t a2 = packbf(A[h][2].x, A[h][2].y);
            uint32_t a3 = packbf(A[h][3].x, A[h][3].y);
#pragma unroll
            for (int j = 0; j < 6; j++) {
                uint32_t b0 = h ? bf[j].z : bf[j].x;
                uint32_t b1 = h ? bf[j].w : bf[j].y;
                mma16816(d[j], a0, a1, a2, a3, b0, b1);
            }
        }
    }

    // Epilogue: D frag (g, 2c) / (g+8, 2c), add bias, float2 stores
    float* dst0 = g_scores + (m0 + g) * TT;
    float* dst1 = dst0 + 8 * TT;
#pragma unroll
    for (int j = 0; j < 6; j++) {
        *reinterpret_cast<float2*>(dst0 + 8 * j + 2 * c) =
            make_float2(d[j][0] + bias2[j].x, d[j][1] + bias2[j].y);
        *reinterpret_cast<float2*>(dst1 + 8 * j + 2 * c) =
            make_float2(d[j][2] + bias2[j].x, d[j][3] + bias2[j].y);
    }
}

// ---------------------------------------------------------------------------
// Fused scan + numerator. Block = 96 threads per batch:
//   warps 0-1 (threads 0-63, states t<48 active): forward scan, linear domain.
//     v'[t'] = (sum_t v[t]*E[t][t']) * 2^{-e(v0)} * exp(emit[t'])
//     e(v0) from exponent bits (exact), accumulated in int Ce.
//     bar.sync 1,64 keeps the scan loop independent of the numerator warp.
//   warp 2 (threads 64-95): numerator gathers + warp reduce.
// out[b] = num - (Ce*ln2 + log(sum_t v[t]*exp(end[t])))
// ---------------------------------------------------------------------------
__global__ void scan_kernel(const float* __restrict__ trans,
                            const float* __restrict__ startT,
                            const float* __restrict__ endT,
                            const int* __restrict__ tag,
                            const int* __restrict__ s_len,
                            float* __restrict__ out) {
    const int b = blockIdx.x;
    const int t = threadIdx.x;
    __shared__ __align__(16) float vbuf[2][64];
    __shared__ float red[TT];
    __shared__ float s_num;

    const int len = s_len[b];
    const float* sc = g_scores + (size_t)b * SS * TT;

    int cur = 0;
    int Ce = 0;

    if (t < 64) {
        const bool act = t < TT;
        const int tc = act ? t : 0;

        float E[TT];
#pragma unroll
        for (int k = 0; k < TT; k++)
            E[k] = act ? __expf(trans[k * TT + t]) : 0.f;

        vbuf[0][t] = act ? __expf(startT[t] + sc[t]) : 0.f;

        float e1 = sc[1 * TT + tc];
        float e2 = sc[2 * TT + tc];
        float x1 = __expf(e1);
        asm volatile("bar.sync 1, 64;" ::: "memory");

        for (int s = 1; s < len; ++s) {
            float ex = x1;
            float en = e2;
            int sp = s + 2; if (sp > SS - 1) sp = SS - 1;
            e2 = sc[sp * TT + tc];
            x1 = __expf(en);

            const float4* vp = reinterpret_cast<const float4*>(vbuf[cur]);
            float4 q0 = vp[0], q1 = vp[1];
            float v0 = q0.x;
            float a0 = q0.x * E[0], a1 = q0.y * E[1];
            float a2 = q0.z * E[2], a3 = q0.w * E[3];
            float a4 = q1.x * E[4], a5 = q1.y * E[5];
            float a6 = q1.z * E[6], a7 = q1.w * E[7];
#pragma unroll
            for (int j = 2; j < 12; j += 2) {
                float4 p1 = vp[j], p2 = vp[j + 1];
                a0 = fmaf(p1.x, E[4 * j + 0], a0);
                a1 = fmaf(p1.y, E[4 * j + 1], a1);
                a2 = fmaf(p1.z, E[4 * j + 2], a2);
                a3 = fmaf(p1.w, E[4 * j + 3], a3);
                a4 = fmaf(p2.x, E[4 * j + 4], a4);
                a5 = fmaf(p2.y, E[4 * j + 5], a5);
                a6 = fmaf(p2.z, E[4 * j + 6], a6);
                a7 = fmaf(p2.w, E[4 * j + 7], a7);
            }
            float dot = ((a0 + a1) + (a2 + a3)) + ((a4 + a5) + (a6 + a7));

            int eb = (__float_as_int(v0) >> 23) & 0xff;      // biased exponent
            Ce += eb - 127;
            float scale = __int_as_float((254 - eb) << 23);  // exact 2^{127-eb}
            float nv = dot * scale * ex;

            vbuf[cur ^ 1][t] = nv;
            asm volatile("bar.sync 1, 64;" ::: "memory");
            cur ^= 1;
        }
        if (act) red[t] = vbuf[cur][t] * __expf(endT[t]);
    } else {
        // warp 2: numerator
        const int l = t - 64;
        const int* tg = tag + b * SS;
        float local = 0.f;
        for (int s = l; s < len; s += 32) {
            int tc2 = tg[s];
            local += sc[s * TT + tc2];
            if (s >= 1) local += trans[tg[s - 1] * TT + tc2];
        }
        if (l == 0) local += startT[tg[0]] + endT[tg[len - 1]];
#pragma unroll
        for (int o = 16; o > 0; o >>= 1)
            local += __shfl_down_sync(0xffffffffu, local, o);
        if (l == 0) s_num = local;
    }
    __syncthreads();

    if (t == 0) {
        float ssum = 0.f;
#pragma unroll
        for (int k = 0; k < TT; k++) ssum += red[k];
        float logZ = (float)Ce * 0.6931471805599453f + __logf(ssum);
        out[b] = s_num - logZ;
    }
}

// ---------------------------------------------------------------------------
// Launch. Inputs: H, W, b, start_transitions, end_transitions, transitions,
// tag(int32), s_len(int32), w_mask (unused: mask == s < s_len).
// ---------------------------------------------------------------------------
extern "C" void kernel_launch(void* const* d_in, const int* in_sizes, int n_in,
                              void* d_out, int out_size) {
    const float* H      = (const float*)d_in[0];
    const float* W      = (const float*)d_in[1];
    const float* bias   = (const float*)d_in[2];
    const float* startT = (const float*)d_in[3];
    const float* endT   = (const float*)d_in[4];
    const float* trans  = (const float*)d_in[5];
    const int*   tag    = (const int*)d_in[6];
    const int*   s_len  = (const int*)d_in[7];
    (void)in_sizes; (void)n_in; (void)out_size;
    float* out = (float*)d_out;

    wfrag_kernel<<<48, 256>>>(W);
    gemm_mma<<<(BB * SS) / 128, 256>>>(H, bias);
    scan_kernel<<<BB, 96>>>(trans, startT, endT, tag, s_len, out);
}